// round 2
// baseline (speedup 1.0000x reference)
#include <cuda_runtime.h>
#include <cuda_bf16.h>
#include <cstdint>

// ---------------- problem constants ----------------
#define TOKENS   32768
#define HIDDEN   5120
#define NEXP     160
#define NGROUP   8
#define EPG      20
#define TOPK     6
#define KCHUNK   64
#define NCHUNKS  (HIDDEN / KCHUNK)   // 80
#define MTILE    128
#define NTHREADS 256

// ---------------- smem layout ----------------
// A tiles: buf(2) x hi/lo(2) x [128 rows x 128B] = 4 x 16384
// B tiles: buf(2) x hi/lo(2) x [160 rows x 128B] = 4 x 20480
#define SA_OFF(buf, hl) ((buf) * 32768 + (hl) * 16384)
#define SB_OFF(buf, hl) (65536 + (buf) * 40960 + (hl) * 20480)
#define SMEM_BYTES 147456
#define BTILE_BYTES 20480
#define EPI_STRIDE 162   // f32 per row, even -> float2 aligned, 2-way conflicts only

// ---------------- device scratch: pre-split, pre-swizzled W -----------------
__device__ __align__(16) unsigned char g_whi[NCHUNKS * BTILE_BYTES];
__device__ __align__(16) unsigned char g_wlo[NCHUNKS * BTILE_BYTES];

// ---------------- helpers ----------------
__device__ __forceinline__ uint32_t smem_u32(const void* p) {
    uint32_t a;
    asm("{ .reg .u64 t; cvta.to.shared.u64 t, %1; cvt.u32.u64 %0, t; }"
        : "=r"(a) : "l"(p));
    return a;
}

__device__ __forceinline__ uint32_t bf2_bits(__nv_bfloat162 h) {
    return *reinterpret_cast<uint32_t*>(&h);
}

#define LDSM_X4(r0, r1, r2, r3, addr) \
    asm volatile("ldmatrix.sync.aligned.m8n8.x4.shared.b16 {%0,%1,%2,%3}, [%4];" \
                 : "=r"(r0), "=r"(r1), "=r"(r2), "=r"(r3) : "r"(addr))

#define LDSM_X2(r0, r1, addr) \
    asm volatile("ldmatrix.sync.aligned.m8n8.x2.shared.b16 {%0,%1}, [%2];" \
                 : "=r"(r0), "=r"(r1) : "r"(addr))

#define MMA16816(d, a0, a1, a2, a3, b0, b1) \
    asm volatile("mma.sync.aligned.m16n8k16.row.col.f32.bf16.bf16.f32 " \
                 "{%0,%1,%2,%3}, {%4,%5,%6,%7}, {%8,%9}, {%0,%1,%2,%3};" \
                 : "+f"((d)[0]), "+f"((d)[1]), "+f"((d)[2]), "+f"((d)[3]) \
                 : "r"(a0), "r"(a1), "r"(a2), "r"(a3), "r"(b0), "r"(b1))

#define CP_ASYNC16(saddr, gptr) \
    asm volatile("cp.async.cg.shared.global [%0], [%1], 16;" \
                 :: "r"(saddr), "l"(gptr))
#define CP_COMMIT() asm volatile("cp.async.commit_group;" ::: "memory")
#define CP_WAIT0()  asm volatile("cp.async.wait_group 0;" ::: "memory")

// ---------------- prep: split W fp32 -> (hi,lo) bf16, pre-swizzled ---------
__global__ void prep_w_kernel(const float* __restrict__ w) {
    int idx = blockIdx.x * 256 + threadIdx.x;
    if (idx >= NEXP * (HIDDEN / 8)) return;
    int n  = idx / (HIDDEN / 8);
    int k8 = idx - n * (HIDDEN / 8);
    int k  = k8 * 8;
    const float4* src = reinterpret_cast<const float4*>(w + (size_t)n * HIDDEN + k);
    float4 v0 = src[0], v1 = src[1];

    __nv_bfloat162 h0 = __floats2bfloat162_rn(v0.x, v0.y);
    __nv_bfloat162 h1 = __floats2bfloat162_rn(v0.z, v0.w);
    __nv_bfloat162 h2 = __floats2bfloat162_rn(v1.x, v1.y);
    __nv_bfloat162 h3 = __floats2bfloat162_rn(v1.z, v1.w);
    __nv_bfloat162 l0 = __floats2bfloat162_rn(v0.x - __bfloat162float(h0.x),
                                              v0.y - __bfloat162float(h0.y));
    __nv_bfloat162 l1 = __floats2bfloat162_rn(v0.z - __bfloat162float(h1.x),
                                              v0.w - __bfloat162float(h1.y));
    __nv_bfloat162 l2 = __floats2bfloat162_rn(v1.x - __bfloat162float(h2.x),
                                              v1.y - __bfloat162float(h2.y));
    __nv_bfloat162 l3 = __floats2bfloat162_rn(v1.z - __bfloat162float(h3.x),
                                              v1.w - __bfloat162float(h3.y));

    int c   = k >> 6;
    int col = k & 63;
    uint32_t off = (uint32_t)(n * 128 + col * 2);
    uint32_t sw  = off ^ ((off >> 3) & 0x70);

    uint4 hv = make_uint4(bf2_bits(h0), bf2_bits(h1), bf2_bits(h2), bf2_bits(h3));
    uint4 lv = make_uint4(bf2_bits(l0), bf2_bits(l1), bf2_bits(l2), bf2_bits(l3));
    *reinterpret_cast<uint4*>(g_whi + (size_t)c * BTILE_BYTES + sw) = hv;
    *reinterpret_cast<uint4*>(g_wlo + (size_t)c * BTILE_BYTES + sw) = lv;
}

// ---------------- main fused kernel ----------------------------------------
__global__ __launch_bounds__(NTHREADS, 1)
void moe_gate_kernel(const float* __restrict__ x, float* __restrict__ out) {
    extern __shared__ __align__(1024) char smem[];
    const uint32_t sb = smem_u32(smem);
    const int tid  = threadIdx.x;
    const int lane = tid & 31;
    const int wid  = tid >> 5;
    const int wm   = wid >> 2;       // 0..1 : M half
    const int wn   = wid & 3;        // 0..3 : N quarter (40 experts)
    const int m0   = blockIdx.x * MTILE;

    // producer mapping: thread covers (rows rg+16*it, cols 4g..4g+3 fp32)
    const int g  = tid & 15;
    const int rg = tid >> 4;
    const float* xbase = x + (size_t)m0 * HIDDEN + (size_t)rg * HIDDEN + g * 4;

    // STS offsets (within a 16KB A tile), same every chunk
    uint32_t sts_off[8];
#pragma unroll
    for (int it = 0; it < 8; ++it) {
        int row = rg + it * 16;
        sts_off[it] = (uint32_t)(row * 128) + (((uint32_t)(g * 8)) ^ ((uint32_t)(row & 7) << 4));
    }

    // ldmatrix lane geometry
    const int grp = lane >> 3;
    const int lr  = lane & 7;

    // A ldmatrix row (per mi): row = wm*64 + mi*16 + (grp&1)*8 + lr
    uint32_t a_row_off[4], a_swm[4];
#pragma unroll
    for (int mi = 0; mi < 4; ++mi) {
        int row = wm * 64 + mi * 16 + (grp & 1) * 8 + lr;
        a_row_off[mi] = (uint32_t)(row * 128);
        a_swm[mi]     = (uint32_t)(row & 7) << 4;
    }
    const int a_segadd = (grp >> 1);   // seg = 2s + a_segadd

    // B ldmatrix rows: x4 pair p: n = wn*40 + p*16 + (grp>>1)*8 + lr ; seg = 2s + (grp&1)
    uint32_t b_row_off[2], b_swm[2];
#pragma unroll
    for (int p = 0; p < 2; ++p) {
        int n = wn * 40 + p * 16 + (grp >> 1) * 8 + lr;
        b_row_off[p] = (uint32_t)(n * 128);
        b_swm[p]     = (uint32_t)(n & 7) << 4;
    }
    const int b_segadd = (grp & 1);
    // x2 tail (n32..39): lanes 0-15 meaningful
    {
    }
    int n2 = wn * 40 + 32 + ((lane & 15) & 7);
    const uint32_t b2_row_off = (uint32_t)(n2 * 128);
    const uint32_t b2_swm     = (uint32_t)(n2 & 7) << 4;
    const int b2_segadd = ((lane & 15) >> 3);

    float acc[4][5][4];
#pragma unroll
    for (int mi = 0; mi < 4; ++mi)
#pragma unroll
        for (int nj = 0; nj < 5; ++nj)
#pragma unroll
            for (int q = 0; q < 4; ++q) acc[mi][nj][q] = 0.f;

    float4 xv[8];

    // ---------------- prologue: stage chunk 0 ----------------
    {
        // B chunk 0 via cp.async
#pragma unroll
        for (int i = 0; i < 5; ++i) {
            uint32_t o = (uint32_t)(i * 256 + tid) * 16;
            CP_ASYNC16(sb + SB_OFF(0, 0) + o, g_whi + o);
            CP_ASYNC16(sb + SB_OFF(0, 1) + o, g_wlo + o);
        }
        CP_COMMIT();
        // A chunk 0
#pragma unroll
        for (int it = 0; it < 8; ++it)
            xv[it] = *reinterpret_cast<const float4*>(xbase + (size_t)(it * 16) * HIDDEN);
#pragma unroll
        for (int it = 0; it < 8; ++it) {
            float4 v = xv[it];
            uint32_t h01 = bf2_bits(__floats2bfloat162_rn(v.x, v.y));
            uint32_t h23 = bf2_bits(__floats2bfloat162_rn(v.z, v.w));
            float hx = __uint_as_float(h01 << 16), hy = __uint_as_float(h01 & 0xffff0000u);
            float hz = __uint_as_float(h23 << 16), hw = __uint_as_float(h23 & 0xffff0000u);
            uint32_t l01 = bf2_bits(__floats2bfloat162_rn(v.x - hx, v.y - hy));
            uint32_t l23 = bf2_bits(__floats2bfloat162_rn(v.z - hz, v.w - hw));
            *reinterpret_cast<uint2*>(smem + SA_OFF(0, 0) + sts_off[it]) = make_uint2(h01, h23);
            *reinterpret_cast<uint2*>(smem + SA_OFF(0, 1) + sts_off[it]) = make_uint2(l01, l23);
        }
        CP_WAIT0();
        __syncthreads();
    }

    // ---------------- main loop ----------------
    int buf = 0;
    for (int c = 0; c < NCHUNKS; ++c) {
        const bool more = (c + 1 < NCHUNKS);
        if (more) {
            // issue B(c+1)
            const size_t bo = (size_t)(c + 1) * BTILE_BYTES;
#pragma unroll
            for (int i = 0; i < 5; ++i) {
                uint32_t o = (uint32_t)(i * 256 + tid) * 16;
                CP_ASYNC16(sb + SB_OFF(buf ^ 1, 0) + o, g_whi + bo + o);
                CP_ASYNC16(sb + SB_OFF(buf ^ 1, 1) + o, g_wlo + bo + o);
            }
            CP_COMMIT();
            // LDG A(c+1)
            const float* xc = xbase + (size_t)(c + 1) * KCHUNK;
#pragma unroll
            for (int it = 0; it < 8; ++it)
                xv[it] = *reinterpret_cast<const float4*>(xc + (size_t)(it * 16) * HIDDEN);
        }

        // ---- compute on buf ----
        const uint32_t aHi = sb + SA_OFF(buf, 0);
        const uint32_t aLo = sb + SA_OFF(buf, 1);
        const uint32_t bHi = sb + SB_OFF(buf, 0);
        const uint32_t bLo = sb + SB_OFF(buf, 1);
#pragma unroll
        for (int s = 0; s < 4; ++s) {
            // B fragments (hi & lo): 5 n8-tiles each
            uint32_t bh[10], bl[10];
#pragma unroll
            for (int p = 0; p < 2; ++p) {
                uint32_t seg = (uint32_t)(2 * s + b_segadd) << 4;
                uint32_t off = b_row_off[p] + (seg ^ b_swm[p]);
                LDSM_X4(bh[4 * p + 0], bh[4 * p + 1], bh[4 * p + 2], bh[4 * p + 3], bHi + off);
                LDSM_X4(bl[4 * p + 0], bl[4 * p + 1], bl[4 * p + 2], bl[4 * p + 3], bLo + off);
            }
            {
                uint32_t seg = (uint32_t)(2 * s + b2_segadd) << 4;
                uint32_t off = b2_row_off + (seg ^ b2_swm);
                LDSM_X2(bh[8], bh[9], bHi + off);
                LDSM_X2(bl[8], bl[9], bLo + off);
            }
#pragma unroll
            for (int mi = 0; mi < 4; ++mi) {
                uint32_t seg = (uint32_t)(2 * s + a_segadd) << 4;
                uint32_t off = a_row_off[mi] + (seg ^ a_swm[mi]);
                uint32_t ah0, ah1, ah2, ah3, al0, al1, al2, al3;
                LDSM_X4(ah0, ah1, ah2, ah3, aHi + off);
                LDSM_X4(al0, al1, al2, al3, aLo + off);
#pragma unroll
                for (int nj = 0; nj < 5; ++nj) {
                    MMA16816(acc[mi][nj], ah0, ah1, ah2, ah3, bh[2 * nj], bh[2 * nj + 1]);
                    MMA16816(acc[mi][nj], ah0, ah1, ah2, ah3, bl[2 * nj], bl[2 * nj + 1]);
                    MMA16816(acc[mi][nj], al0, al1, al2, al3, bh[2 * nj], bh[2 * nj + 1]);
                }
            }
        }

        if (more) {
            // convert + store A(c+1)
#pragma unroll
            for (int it = 0; it < 8; ++it) {
                float4 v = xv[it];
                uint32_t h01 = bf2_bits(__floats2bfloat162_rn(v.x, v.y));
                uint32_t h23 = bf2_bits(__floats2bfloat162_rn(v.z, v.w));
                float hx = __uint_as_float(h01 << 16), hy = __uint_as_float(h01 & 0xffff0000u);
                float hz = __uint_as_float(h23 << 16), hw = __uint_as_float(h23 & 0xffff0000u);
                uint32_t l01 = bf2_bits(__floats2bfloat162_rn(v.x - hx, v.y - hy));
                uint32_t l23 = bf2_bits(__floats2bfloat162_rn(v.z - hz, v.w - hw));
                *reinterpret_cast<uint2*>(smem + SA_OFF(buf ^ 1, 0) + sts_off[it]) = make_uint2(h01, h23);
                *reinterpret_cast<uint2*>(smem + SA_OFF(buf ^ 1, 1) + sts_off[it]) = make_uint2(l01, l23);
            }
            CP_WAIT0();
        }
        __syncthreads();
        buf ^= 1;
    }

    // ---------------- accs -> smem (logits) ----------------
    float* lg = reinterpret_cast<float*>(smem);
#pragma unroll
    for (int mi = 0; mi < 4; ++mi) {
        int r0 = wm * 64 + mi * 16 + (lane >> 2);
#pragma unroll
        for (int nj = 0; nj < 5; ++nj) {
            int cb = wn * 40 + nj * 8 + (lane & 3) * 2;
            *reinterpret_cast<float2*>(lg + (size_t)r0 * EPI_STRIDE + cb) =
                make_float2(acc[mi][nj][0], acc[mi][nj][1]);
            *reinterpret_cast<float2*>(lg + (size_t)(r0 + 8) * EPI_STRIDE + cb) =
                make_float2(acc[mi][nj][2], acc[mi][nj][3]);
        }
    }
    __syncthreads();

    // ---------------- epilogue: softmax + grouped top-k (1 thread/token) ---
    if (tid < MTILE) {
        float z[NEXP];
#pragma unroll
        for (int e = 0; e < NEXP; e += 2) {
            float2 v = *reinterpret_cast<float2*>(lg + (size_t)tid * EPI_STRIDE + e);
            z[e] = v.x; z[e + 1] = v.y;
        }
        float mx = -3.4e38f;
#pragma unroll
        for (int e = 0; e < NEXP; ++e) mx = fmaxf(mx, z[e]);
        float sum = 0.f;
#pragma unroll
        for (int e = 0; e < NEXP; ++e) {
            float p = __expf(z[e] - mx);
            sum += p;
            z[e] = p;
        }
        float gmx[NGROUP];
#pragma unroll
        for (int q = 0; q < NGROUP; ++q) {
            float m = 0.f;
#pragma unroll
            for (int t = 0; t < EPG; ++t) m = fmaxf(m, z[q * EPG + t]);
            gmx[q] = m;
        }
        float t1 = 0.f, t2 = 0.f, t3 = 0.f;
#pragma unroll
        for (int q = 0; q < NGROUP; ++q) t1 = fmaxf(t1, gmx[q]);
#pragma unroll
        for (int q = 0; q < NGROUP; ++q) t2 = fmaxf(t2, (gmx[q] < t1) ? gmx[q] : 0.f);
#pragma unroll
        for (int q = 0; q < NGROUP; ++q) t3 = fmaxf(t3, (gmx[q] < t2) ? gmx[q] : 0.f);
#pragma unroll
        for (int e = 0; e < NEXP; ++e)
            z[e] = (gmx[e / EPG] >= t3) ? z[e] : 0.f;

        const float inv = 16.0f / sum;
        float* orow = out + (size_t)(m0 + tid) * TOPK;
        float prev = 3.4e38f;
#pragma unroll
        for (int i = 0; i < TOPK; ++i) {
            float cur = 0.f;
#pragma unroll
            for (int e = 0; e < NEXP; ++e)
                cur = fmaxf(cur, (z[e] < prev) ? z[e] : 0.f);
            orow[i] = cur * inv;
            prev = cur;
        }
    }
}

// ---------------- launch ----------------------------------------------------
extern "C" void kernel_launch(void* const* d_in, const int* in_sizes, int n_in,
                              void* d_out, int out_size) {
    const float* x = (const float*)d_in[0];   // [32768, 5120] fp32
    const float* w = (const float*)d_in[1];   // [160, 5120] fp32
    float* out = (float*)d_out;               // [32768, 6] fp32

    cudaFuncSetAttribute(moe_gate_kernel,
                         cudaFuncAttributeMaxDynamicSharedMemorySize, SMEM_BYTES);

    int prep_elems = NEXP * (HIDDEN / 8);
    prep_w_kernel<<<(prep_elems + 255) / 256, 256>>>(w);
    moe_gate_kernel<<<TOKENS / MTILE, NTHREADS, SMEM_BYTES>>>(x, out);
}